// round 2
// baseline (speedup 1.0000x reference)
#include <cuda_runtime.h>
#include <math.h>

// Problem constants
#define NQ   32768      // N*S1*S2
#define MOFF 27

// Attention tiling: 16 queries (4a x 4b), halo 3n x 6a x 6b
#define HSZ  108
#define WSTR 68                    // padded weight row stride (floats)
#define WMAT (64 * WSTR)           // 4352 floats per transposed 64x64 matrix
// smem: h halo (108*64) + 2 double-buffered (wk,wv) matrices
#define ATTN_SMEM_FLOATS (HSZ * 64 + 4 * WMAT)
#define ATTN_SMEM (ATTN_SMEM_FLOATS * 4)   // 97280 bytes

// Scratch (static device globals: allocation-free per harness rules)
__device__ float g_h0[NQ * 64];
__device__ float g_h1[NQ * 64];
__device__ float g_stats[8];            // mean[0..2], rsigma[4..6]
__device__ float g_wqt[2 * WMAT];       // transposed+padded Wq per layer
__device__ float g_wkt[54 * WMAT];      // transposed+padded Wk  (2 layers x 27)
__device__ float g_wvt[54 * WMAT];      // transposed+padded Wv

typedef unsigned long long ull;

__device__ __forceinline__ ull pack2(float x, float y) {
    ull r;
    asm("mov.b64 %0, {%1, %2};" : "=l"(r) : "r"(__float_as_uint(x)), "r"(__float_as_uint(y)));
    return r;
}
__device__ __forceinline__ void unpack2(ull p, float& x, float& y) {
    unsigned lo, hi;
    asm("mov.b64 {%0, %1}, %2;" : "=r"(lo), "=r"(hi) : "l"(p));
    x = __uint_as_float(lo); y = __uint_as_float(hi);
}
// Packed dual FP32 FMA (Blackwell FFMA2)
__device__ __forceinline__ ull ffma2(ull a, ull b, ull c) {
    ull d;
    asm("fma.rn.f32x2 %0, %1, %2, %3;" : "=l"(d) : "l"(a), "l"(b), "l"(c));
    return d;
}
__device__ __forceinline__ void cp_async16(float* dst, const float* src) {
    unsigned d = (unsigned)__cvta_generic_to_shared(dst);
    asm volatile("cp.async.cg.shared.global [%0], [%1], 16;" :: "r"(d), "l"(src));
}
__device__ __forceinline__ void cp_commit() {
    asm volatile("cp.async.commit_group;" ::: "memory");
}
__device__ __forceinline__ void cp_wait1() {
    asm volatile("cp.async.wait_group 1;" ::: "memory");
}

// ---------------------------------------------------------------------------
// 0) Transpose + pad weights: w_t[mi][d*68 + c] = W[mi][c*64 + d]
// ---------------------------------------------------------------------------
__global__ void transpose_w_kernel(const float* __restrict__ Wq,
                                   const float* __restrict__ Wk,
                                   const float* __restrict__ Wv) {
    int idx = blockIdx.x * 256 + threadIdx.x;
    if (idx < 54 * 4096) {
        int mi = idx >> 12, e = idx & 4095, cc = e >> 6, dd = e & 63;
        int o = mi * WMAT + dd * WSTR + cc;
        g_wkt[o] = Wk[idx];
        g_wvt[o] = Wv[idx];
    }
    if (idx < 2 * 4096) {
        int mi = idx >> 12, e = idx & 4095, cc = e >> 6, dd = e & 63;
        g_wqt[mi * WMAT + dd * WSTR + cc] = Wq[idx];
    }
}

// ---------------------------------------------------------------------------
// 1) BatchNorm batch statistics
// ---------------------------------------------------------------------------
__global__ void bn_stats_kernel(const float* __restrict__ x) {
    float s0 = 0.f, s1 = 0.f, s2 = 0.f, t0 = 0.f, t1 = 0.f, t2 = 0.f;
    for (int p = threadIdx.x; p < NQ; p += 1024) {
        float v0 = x[p * 3 + 0], v1 = x[p * 3 + 1], v2 = x[p * 3 + 2];
        s0 += v0; s1 += v1; s2 += v2;
        t0 += v0 * v0; t1 += v1 * v1; t2 += v2 * v2;
    }
#pragma unroll
    for (int o = 16; o; o >>= 1) {
        s0 += __shfl_xor_sync(0xffffffffu, s0, o);
        s1 += __shfl_xor_sync(0xffffffffu, s1, o);
        s2 += __shfl_xor_sync(0xffffffffu, s2, o);
        t0 += __shfl_xor_sync(0xffffffffu, t0, o);
        t1 += __shfl_xor_sync(0xffffffffu, t1, o);
        t2 += __shfl_xor_sync(0xffffffffu, t2, o);
    }
    __shared__ float red[32][6];
    int lane = threadIdx.x & 31, w = threadIdx.x >> 5;
    if (lane == 0) {
        red[w][0] = s0; red[w][1] = s1; red[w][2] = s2;
        red[w][3] = t0; red[w][4] = t1; red[w][5] = t2;
    }
    __syncthreads();
    if (threadIdx.x < 32) {
        float a0 = red[lane][0], a1 = red[lane][1], a2 = red[lane][2];
        float a3 = red[lane][3], a4 = red[lane][4], a5 = red[lane][5];
#pragma unroll
        for (int o = 16; o; o >>= 1) {
            a0 += __shfl_xor_sync(0xffffffffu, a0, o);
            a1 += __shfl_xor_sync(0xffffffffu, a1, o);
            a2 += __shfl_xor_sync(0xffffffffu, a2, o);
            a3 += __shfl_xor_sync(0xffffffffu, a3, o);
            a4 += __shfl_xor_sync(0xffffffffu, a4, o);
            a5 += __shfl_xor_sync(0xffffffffu, a5, o);
        }
        if (lane == 0) {
            const float inv = 1.0f / (float)NQ;
            float m0 = a0 * inv, m1 = a1 * inv, m2 = a2 * inv;
            g_stats[0] = m0; g_stats[1] = m1; g_stats[2] = m2;
            g_stats[4] = rsqrtf(a3 * inv - m0 * m0 + 1e-5f);
            g_stats[5] = rsqrtf(a4 * inv - m1 * m1 + 1e-5f);
            g_stats[6] = rsqrtf(a5 * inv - m2 * m2 + 1e-5f);
        }
    }
}

// ---------------------------------------------------------------------------
// 2) h0 = normalize(x) @ W_in + b_in
// ---------------------------------------------------------------------------
__global__ void input_proj_kernel(const float* __restrict__ x,
                                  const float* __restrict__ W_in,
                                  const float* __restrict__ b_in,
                                  float* __restrict__ h_out) {
    int idx = blockIdx.x * 256 + threadIdx.x;
    int p = idx >> 6, c = idx & 63;
    float acc = b_in[c];
#pragma unroll
    for (int f = 0; f < 3; f++) {
        float xn = (x[p * 3 + f] - g_stats[f]) * g_stats[4 + f];
        acc += xn * W_in[f * 64 + c];
    }
    h_out[idx] = acc;
}

// ---------------------------------------------------------------------------
// 3) Fused attention layer.
//    128 threads: warp&1 selects channel half (c = 32*(warp&1)+lane),
//    warp>>1 selects query row-pair slot. Thread handles 8 queries, 1 channel.
//    Dot products use packed FFMA2 over input-channel pairs.
// ---------------------------------------------------------------------------
__global__ __launch_bounds__(128)
void attn_kernel(const float* __restrict__ h_in, float* __restrict__ h_out,
                 const float* __restrict__ wqt, const float* __restrict__ bq,
                 const float* __restrict__ wkt, const float* __restrict__ bk,
                 const float* __restrict__ wvt, const float* __restrict__ bv) {
    extern __shared__ float smem[];
    float* h_s  = smem;                 // HSZ * 64
    float* wbuf = smem + HSZ * 64;      // 4 * WMAT (double-buffered wk,wv)

    const int tid  = threadIdx.x;
    const int lane = tid & 31;
    const int warp = tid >> 5;                 // 0..3
    const int c    = ((warp & 1) << 5) + lane; // output channel 0..63
    const int slot = warp >> 1;                // 0..1

    const int bx = blockIdx.x;
    const int tn = bx >> 6;
    const int r  = bx & 63;
    const int a0 = (r >> 3) << 2;
    const int b0 = (r & 7) << 2;

    // --- halo load (float4, zero OOB) ---
    for (int idx = tid; idx < HSZ * 16; idx += 128) {
        int pos = idx >> 4, c4 = idx & 15;
        int hn = pos / 36, rem = pos - hn * 36;
        int ha = rem / 6, hb = rem - ha * 6;
        int gn = tn - 1 + hn, ga = a0 - 1 + ha, gb = b0 - 1 + hb;
        float4 v = make_float4(0.f, 0.f, 0.f, 0.f);
        if ((unsigned)gn < 32u && (unsigned)ga < 32u && (unsigned)gb < 32u)
            v = *(const float4*)&h_in[(((gn * 32 + ga) * 32 + gb) << 6) + (c4 << 2)];
        *(float4*)&h_s[(pos << 6) + (c4 << 2)] = v;
    }
    // stage transposed Wq into wbuf[0]
    for (int j = tid; j < WMAT / 4; j += 128)
        *(float4*)&wbuf[j << 2] = *(const float4*)&wqt[j << 2];
    __syncthreads();

    // --- per-thread query geometry (8 queries: 2 qa rows x 4 qb) ---
    int qc[8], gaq[8], gbq[8];
#pragma unroll
    for (int i = 0; i < 8; i++) {
        int qa = (slot << 1) + (i >> 2);
        int qb = i & 3;
        gaq[i] = a0 + qa; gbq[i] = b0 + qb;
        qc[i]  = (7 + qa) * 6 + 1 + qb;     // center halo index (hn=1)
    }

    // --- q projection: q[c] for 8 queries ---
    float qv[8];
    {
        ull acc[8];
        ull binit = pack2(bq[c], 0.0f);
#pragma unroll
        for (int i = 0; i < 8; i++) acc[i] = binit;
#pragma unroll
        for (int cp = 0; cp < 64; cp += 4) {
            ulonglong2 w2 = *(const ulonglong2*)&wbuf[c * WSTR + cp];
#pragma unroll
            for (int i = 0; i < 8; i++) {
                ulonglong2 hh = *(const ulonglong2*)&h_s[(qc[i] << 6) + cp];
                acc[i] = ffma2(hh.x, w2.x, acc[i]);
                acc[i] = ffma2(hh.y, w2.y, acc[i]);
            }
        }
#pragma unroll
        for (int i = 0; i < 8; i++) {
            float x, y; unpack2(acc[i], x, y);
            qv[i] = x + y;
        }
    }
    __syncthreads();   // done with wbuf[0] before prefetch overwrites

    // --- prefetch weights for offset 0 into buffer 0 ---
    {
        const float* gk = wkt;
        const float* gv = wvt;
        for (int j = tid; j < WMAT / 4; j += 128) {
            cp_async16(&wbuf[j << 2],        gk + (j << 2));
            cp_async16(&wbuf[WMAT + (j << 2)], gv + (j << 2));
        }
        cp_commit();
    }

    const float NEG_INF = __int_as_float(0xff800000);
    float mx[8], den[8], oacc[8];
#pragma unroll
    for (int i = 0; i < 8; i++) { mx[i] = NEG_INF; den[i] = 0.0f; oacc[i] = 0.0f; }

    for (int m = 0; m < MOFF; m++) {
        // prefetch next offset's weights into the other buffer
        if (m < MOFF - 1) {
            int nb = (m + 1) & 1;
            const float* gk = wkt + (m + 1) * WMAT;
            const float* gv = wvt + (m + 1) * WMAT;
            float* sk = wbuf + nb * 2 * WMAT;
            for (int j = tid; j < WMAT / 4; j += 128) {
                cp_async16(sk + (j << 2),        gk + (j << 2));
                cp_async16(sk + WMAT + (j << 2), gv + (j << 2));
            }
        }
        cp_commit();
        cp_wait1();          // buffer for offset m is complete
        __syncthreads();

        const float* wk_s = wbuf + (m & 1) * 2 * WMAT;
        const float* wv_s = wk_s + WMAT;

        int t  = m / 9;
        int r9 = m - t * 9;
        int k1 = r9 / 3, k2 = r9 - k1 * 3;
        int di = k1 - 1, dj = k2 - 1;
        int dofs = (t - 1) * 36 + di * 6 + dj;

        ull kacc[8], vacc[8];
        ull bkp = pack2(bk[m * 64 + c], 0.0f);
        ull bvp = pack2(bv[m * 64 + c], 0.0f);
        int ho[8];
#pragma unroll
        for (int i = 0; i < 8; i++) {
            kacc[i] = bkp; vacc[i] = bvp;
            ho[i] = (qc[i] + dofs) << 6;
        }

#pragma unroll
        for (int cp = 0; cp < 64; cp += 4) {
            ulonglong2 wk2 = *(const ulonglong2*)&wk_s[c * WSTR + cp];
            ulonglong2 wv2 = *(const ulonglong2*)&wv_s[c * WSTR + cp];
#pragma unroll
            for (int i = 0; i < 8; i++) {
                ulonglong2 hh = *(const ulonglong2*)&h_s[ho[i] + cp];
                kacc[i] = ffma2(hh.x, wk2.x, kacc[i]);
                vacc[i] = ffma2(hh.x, wv2.x, vacc[i]);
                kacc[i] = ffma2(hh.y, wk2.y, kacc[i]);
                vacc[i] = ffma2(hh.y, wv2.y, vacc[i]);
            }
        }

#pragma unroll
        for (int i = 0; i < 8; i++) {
            float kx, ky; unpack2(kacc[i], kx, ky);
            float s = (kx + ky) * qv[i];
            // sum over this head's 16 channels (16-lane groups)
            s += __shfl_xor_sync(0xffffffffu, s, 1);
            s += __shfl_xor_sync(0xffffffffu, s, 2);
            s += __shfl_xor_sync(0xffffffffu, s, 4);
            s += __shfl_xor_sync(0xffffffffu, s, 8);
            bool valid = ((unsigned)(gaq[i] + di) < 32u) && ((unsigned)(gbq[i] + dj) < 32u);
            if (!valid) s = -1e30f;     // spatial mask only (time is zero-padded, not masked)
            float nm = fmaxf(mx[i], s);
            float sc = __expf(mx[i] - nm);
            float p  = __expf(s - nm);
            mx[i]  = nm;
            den[i] = den[i] * sc + p;
            float vx, vy; unpack2(vacc[i], vx, vy);
            oacc[i] = oacc[i] * sc + p * (vx + vy);
        }
        __syncthreads();   // all readers done before buffer is overwritten
    }

    // --- epilogue: normalize, residual, write ---
#pragma unroll
    for (int i = 0; i < 8; i++) {
        float res = h_s[(qc[i] << 6) + c];
        int gpos = (tn * 32 + gaq[i]) * 32 + gbq[i];
        h_out[(gpos << 6) + c] = oacc[i] / den[i] + res;
    }
}

// ---------------------------------------------------------------------------
// 4) out = h @ W_out + b_out
// ---------------------------------------------------------------------------
__global__ void out_proj_kernel(const float* __restrict__ h,
                                const float* __restrict__ W_out,
                                const float* __restrict__ b_out,
                                float* __restrict__ out) {
    __shared__ float hs[32 * 64];
    int tid = threadIdx.x;              // 128 threads
    int base = blockIdx.x * 32;
    for (int j = tid; j < 2048; j += 128) hs[j] = h[base * 64 + j];
    __syncthreads();
    if (tid < 96) {
        int rr = tid / 3, f = tid - 3 * (tid / 3);
        float acc = b_out[f];
#pragma unroll 8
        for (int cp = 0; cp < 64; cp++)
            acc += hs[rr * 64 + cp] * W_out[cp * 3 + f];
        out[(base + rr) * 3 + f] = acc;
    }
}

// ---------------------------------------------------------------------------
extern "C" void kernel_launch(void* const* d_in, const int* in_sizes, int n_in,
                              void* d_out, int out_size) {
    const float* x     = (const float*)d_in[0];
    const float* W_in  = (const float*)d_in[1];
    const float* b_in  = (const float*)d_in[2];
    const float* W_out = (const float*)d_in[3];
    const float* b_out = (const float*)d_in[4];
    const float* Wq    = (const float*)d_in[5];
    const float* bq    = (const float*)d_in[6];
    const float* Wk    = (const float*)d_in[7];
    const float* bk    = (const float*)d_in[8];
    const float* Wv    = (const float*)d_in[9];
    const float* bv    = (const float*)d_in[10];
    float* out = (float*)d_out;

    float *h0, *h1, *wqt, *wkt, *wvt;
    cudaGetSymbolAddress((void**)&h0, g_h0);
    cudaGetSymbolAddress((void**)&h1, g_h1);
    cudaGetSymbolAddress((void**)&wqt, g_wqt);
    cudaGetSymbolAddress((void**)&wkt, g_wkt);
    cudaGetSymbolAddress((void**)&wvt, g_wvt);
    cudaFuncSetAttribute(attn_kernel, cudaFuncAttributeMaxDynamicSharedMemorySize, ATTN_SMEM);

    transpose_w_kernel<<<(54 * 4096 + 255) / 256, 256>>>(Wq, Wk, Wv);
    bn_stats_kernel<<<1, 1024>>>(x);
    input_proj_kernel<<<(NQ * 64) / 256, 256>>>(x, W_in, b_in, h0);

    // layer 0: h0 -> h1
    attn_kernel<<<2048, 128, ATTN_SMEM>>>(h0, h1,
        wqt + 0 * WMAT, bq + 0 * 64,
        wkt + 0 * MOFF * WMAT, bk + 0 * MOFF * 64,
        wvt + 0 * MOFF * WMAT, bv + 0 * MOFF * 64);
    // layer 1: h1 -> h0
    attn_kernel<<<2048, 128, ATTN_SMEM>>>(h1, h0,
        wqt + 1 * WMAT, bq + 1 * 64,
        wkt + 1 * MOFF * WMAT, bk + 1 * MOFF * 64,
        wvt + 1 * MOFF * WMAT, bv + 1 * MOFF * 64);

    out_proj_kernel<<<NQ / 32, 128>>>(h0, W_out, b_out, out);
}